// round 8
// baseline (speedup 1.0000x reference)
#include <cuda_runtime.h>
#include <cuda_fp16.h>
#include <cstdint>

// Problem shape (fixed by the reference)
constexpr int BD = 4096;   // batch rows
constexpr int DD = 1024;   // model dim
constexpr int HD = 2048;   // hidden dim
constexpr int ED = 8;      // experts

// GEMM tiling: 128x128x32 CTA tile, 32x32 warp tile, 16 warps (4Mx4N), 2 CTAs/SM.
constexpr int BM = 128, BN = 128, BK = 32;
constexpr int STAGES = 4;                 // prefetch depth 3, wait_group<2>
constexpr int ASTR = BK + 8;              // 40 halves/row
constexpr int BSTR = BN + 8;              // 136 halves/row
constexpr int A_STAGE = BM * ASTR;        // 5120 halves
constexpr int B_STAGE = BK * BSTR;        // 4352 halves
constexpr size_t SMEM_BYTES = (size_t)STAGES * (A_STAGE + B_STAGE) * sizeof(__half); // 75776

// Scratch (allocation-free: __device__ globals)
__device__ __align__(256) __half g_xh [(size_t)BD * DD];
__device__ __align__(256) __half g_w1h[(size_t)ED * DD * HD];
__device__ __align__(256) __half g_w2h[(size_t)ED * HD * DD];
__device__ __align__(256) __half g_h  [(size_t)ED * BD * HD];

// ---------------------------------------------------------------- converts
__global__ void cvt_f32_f16(const float* __restrict__ s, __half* __restrict__ d, int n4) {
    int i = blockIdx.x * blockDim.x + threadIdx.x;
    if (i < n4) {
        float4 v = reinterpret_cast<const float4*>(s)[i];
        reinterpret_cast<__half2*>(d)[2*i]   = __floats2half2_rn(v.x, v.y);
        reinterpret_cast<__half2*>(d)[2*i+1] = __floats2half2_rn(v.z, v.w);
    }
}

// ---------------------------------------------------------------- PTX utils
__device__ __forceinline__ void cp16(uint32_t saddr, const void* g) {
    asm volatile("cp.async.cg.shared.global [%0], [%1], 16;\n" :: "r"(saddr), "l"(g));
}
__device__ __forceinline__ void cp_commit() { asm volatile("cp.async.commit_group;\n"); }
template<int N> __device__ __forceinline__ void cp_wait() {
    asm volatile("cp.async.wait_group %0;\n" :: "n"(N));
}
__device__ __forceinline__ void ldsm4(uint32_t* r, uint32_t saddr) {
    asm volatile("ldmatrix.sync.aligned.m8n8.x4.shared.b16 {%0,%1,%2,%3}, [%4];\n"
        : "=r"(r[0]), "=r"(r[1]), "=r"(r[2]), "=r"(r[3]) : "r"(saddr));
}
__device__ __forceinline__ void ldsm4t(uint32_t* r, uint32_t saddr) {
    asm volatile("ldmatrix.sync.aligned.m8n8.x4.trans.shared.b16 {%0,%1,%2,%3}, [%4];\n"
        : "=r"(r[0]), "=r"(r[1]), "=r"(r[2]), "=r"(r[3]) : "r"(saddr));
}
__device__ __forceinline__ void mma16816(float* c, const uint32_t* a, uint32_t b0, uint32_t b1) {
    asm volatile("mma.sync.aligned.m16n8k16.row.col.f32.f16.f16.f32 "
        "{%0,%1,%2,%3}, {%4,%5,%6,%7}, {%8,%9}, {%0,%1,%2,%3};\n"
        : "+f"(c[0]), "+f"(c[1]), "+f"(c[2]), "+f"(c[3])
        : "r"(a[0]), "r"(a[1]), "r"(a[2]), "r"(a[3]), "r"(b0), "r"(b1));
}

// ---------------------------------------------------------------- GEMM
// C[M,N] = A[M,K] (row-major fp16) * B[K,N] (row-major fp16) per blockIdx.z expert.
// 512 threads: warp w -> warp tile at (wm, wn) = ((w>>2)*32, (w&3)*32).
// MODE 0: out = fp16, relu(C + bias)  (GEMM1 -> h scratch)
// MODE 1: out = fp32, C + bias        (GEMM2 -> final out, strided rows)
template<int MODE>
__global__ __launch_bounds__(512, 2)
void gemm_kernel(const __half* __restrict__ A, const __half* __restrict__ Bm,
                 const float* __restrict__ bias, void* __restrict__ outp,
                 int M, int N, int K,
                 size_t a_zstride, size_t out_zstride, size_t out_rstride)
{
    extern __shared__ __align__(16) __half smem[];
    const int z  = blockIdx.z;
    const int m0 = blockIdx.y * BM;
    const int n0 = blockIdx.x * BN;

    const __half* Az  = A + (size_t)z * a_zstride;
    const __half* Bz  = Bm + (size_t)z * (size_t)K * N;
    const float*  biz = bias + (size_t)z * N;

    const uint32_t sbase = (uint32_t)__cvta_generic_to_shared(smem);
    const uint32_t sA = sbase;
    const uint32_t sB = sbase + (uint32_t)(STAGES * A_STAGE * 2);

    const int tid = threadIdx.x;
    const int lane = tid & 31;
    const int warp = tid >> 5;
    const int wm = (warp >> 2) * 32;          // 4 warps along M
    const int wn = (warp & 3) * 32;           // 4 warps along N
    const int lr = (lane & 7) + ((lane >> 3) & 1) * 8;  // ldmatrix row-in-16
    const int lc = ((lane >> 4) & 1) * 8;               // ldmatrix col-half

    // Per-stage load: A 128x32 halves (512 x 16B), B 32x128 halves (512 x 16B):
    // exactly 2 cp16 per thread.
    auto load_stage = [&](int st, int kt) {
        const __half* Ag = Az + (size_t)m0 * K + (size_t)kt * BK;
        const __half* Bg = Bz + (size_t)kt * BK * N + n0;
        int ar = tid >> 2, ak = (tid & 3) * 8;
        cp16(sA + (uint32_t)(st * A_STAGE + ar * ASTR + ak) * 2,
             Ag + (size_t)ar * K + ak);
        int br = tid >> 4, bn = (tid & 15) * 8;
        cp16(sB + (uint32_t)(st * B_STAGE + br * BSTR + bn) * 2,
             Bg + (size_t)br * N + bn);
    };

    float acc[2][4][4] = {};

    auto compute_stage = [&](int st) {
        #pragma unroll
        for (int ks = 0; ks < BK / 16; ks++) {
            uint32_t af[2][4];
            #pragma unroll
            for (int mt = 0; mt < 2; mt++)
                ldsm4(af[mt], sA + (uint32_t)(st * A_STAGE + (wm + mt*16 + lr) * ASTR + ks*16 + lc) * 2);
            uint32_t bf[2][4];
            #pragma unroll
            for (int nt = 0; nt < 2; nt++)
                ldsm4t(bf[nt], sB + (uint32_t)(st * B_STAGE + (ks*16 + lr) * BSTR + wn + nt*16 + lc) * 2);
            #pragma unroll
            for (int mt = 0; mt < 2; mt++)
                #pragma unroll
                for (int n8 = 0; n8 < 4; n8++)
                    mma16816(acc[mt][n8], af[mt],
                             bf[n8 >> 1][(n8 & 1) * 2], bf[n8 >> 1][(n8 & 1) * 2 + 1]);
        }
    };

    const int KT = K / BK;
    load_stage(0, 0); cp_commit();
    load_stage(1, 1); cp_commit();
    load_stage(2, 2); cp_commit();
    cp_wait<2>();
    __syncthreads();

    int buf = 0;        // stage being computed
    int ldb = 3;        // stage being loaded next (ring)
    for (int kt = 0; kt < KT; kt++) {
        if (kt + 3 < KT) load_stage(ldb, kt + 3);
        cp_commit();
        compute_stage(buf);
        cp_wait<2>();
        __syncthreads();
        buf = (buf + 1) & (STAGES - 1);
        ldb = (ldb + 1) & (STAGES - 1);
    }

    // Epilogue
    const int g = lane >> 2, t4 = lane & 3;
    if (MODE == 0) {
        __half* O = (__half*)outp + (size_t)z * out_zstride;
        #pragma unroll
        for (int mt = 0; mt < 2; mt++) {
            int r0 = m0 + wm + mt * 16 + g;
            #pragma unroll
            for (int n8 = 0; n8 < 4; n8++) {
                int col = n0 + wn + n8 * 8 + 2 * t4;
                float bb0 = biz[col], bb1 = biz[col + 1];
                float v00 = fmaxf(acc[mt][n8][0] + bb0, 0.f);
                float v01 = fmaxf(acc[mt][n8][1] + bb1, 0.f);
                float v10 = fmaxf(acc[mt][n8][2] + bb0, 0.f);
                float v11 = fmaxf(acc[mt][n8][3] + bb1, 0.f);
                *(__half2*)&O[(size_t)r0 * out_rstride + col]       = __floats2half2_rn(v00, v01);
                *(__half2*)&O[(size_t)(r0 + 8) * out_rstride + col] = __floats2half2_rn(v10, v11);
            }
        }
    } else {
        float* O = (float*)outp + (size_t)z * out_zstride;
        #pragma unroll
        for (int mt = 0; mt < 2; mt++) {
            int r0 = m0 + wm + mt * 16 + g;
            #pragma unroll
            for (int n8 = 0; n8 < 4; n8++) {
                int col = n0 + wn + n8 * 8 + 2 * t4;
                float bb0 = biz[col], bb1 = biz[col + 1];
                float2 lo = make_float2(acc[mt][n8][0] + bb0, acc[mt][n8][1] + bb1);
                float2 hi = make_float2(acc[mt][n8][2] + bb0, acc[mt][n8][3] + bb1);
                *(float2*)&O[(size_t)r0 * out_rstride + col]       = lo;
                *(float2*)&O[(size_t)(r0 + 8) * out_rstride + col] = hi;
            }
        }
    }
}

// ---------------------------------------------------------------- launch
extern "C" void kernel_launch(void* const* d_in, const int* in_sizes, int n_in,
                              void* d_out, int out_size) {
    const float* x  = (const float*)d_in[0];   // [B, D]
    const float* W1 = (const float*)d_in[1];   // [E, D, H]
    const float* b1 = (const float*)d_in[2];   // [E, H]
    const float* W2 = (const float*)d_in[3];   // [E, H, D]
    const float* b2 = (const float*)d_in[4];   // [E, D]
    float* out = (float*)d_out;                // [B, E, D]

    __half *xh, *w1h, *w2h, *hbuf;
    cudaGetSymbolAddress((void**)&xh,  g_xh);
    cudaGetSymbolAddress((void**)&w1h, g_w1h);
    cudaGetSymbolAddress((void**)&w2h, g_w2h);
    cudaGetSymbolAddress((void**)&hbuf, g_h);

    cudaFuncSetAttribute(gemm_kernel<0>, cudaFuncAttributeMaxDynamicSharedMemorySize, (int)SMEM_BYTES);
    cudaFuncSetAttribute(gemm_kernel<1>, cudaFuncAttributeMaxDynamicSharedMemorySize, (int)SMEM_BYTES);

    int n4;
    n4 = (BD * DD) / 4;      cvt_f32_f16<<<(n4 + 255) / 256, 256>>>(x,  xh,  n4);
    n4 = (ED * DD * HD) / 4; cvt_f32_f16<<<(n4 + 255) / 256, 256>>>(W1, w1h, n4);
    n4 = (ED * HD * DD) / 4; cvt_f32_f16<<<(n4 + 255) / 256, 256>>>(W2, w2h, n4);

    // GEMM1: h[e,b,:] = relu(x @ W1_e + b1_e), fp16 out
    dim3 g1(HD / BN, BD / BM, ED);
    gemm_kernel<0><<<g1, 512, SMEM_BYTES>>>(xh, w1h, b1, hbuf,
        BD, HD, DD, /*a_zstride=*/0, /*out_zstride=*/(size_t)BD * HD, /*out_rstride=*/HD);

    // GEMM2: out[b,e,:] = h_e @ W2_e + b2_e, fp32 out with row stride E*D
    dim3 g2(DD / BN, BD / BM, ED);
    gemm_kernel<1><<<g2, 512, SMEM_BYTES>>>(hbuf, w2h, b2, out,
        BD, DD, HD, /*a_zstride=*/(size_t)BD * HD, /*out_zstride=*/(size_t)DD,
        /*out_rstride=*/(size_t)ED * DD);
}

// round 9
// speedup vs baseline: 1.0708x; 1.0708x over previous
#include <cuda_runtime.h>
#include <cuda_fp16.h>
#include <cstdint>

// Problem shape (fixed by the reference)
constexpr int BD = 4096;   // batch rows
constexpr int DD = 1024;   // model dim
constexpr int HD = 2048;   // hidden dim
constexpr int ED = 8;      // experts

// GEMM tiling (R5 macro-config): 128x128x32 CTA, 64x32 warp tile, 8 warps, 2 CTAs/SM
constexpr int BM = 128, BN = 128, BK = 32;
constexpr int STAGES = 4;                 // prefetch depth 3, wait_group<2>
constexpr int ASTR = BK + 8;              // 40 halves/row
constexpr int BSTR = BN + 8;              // 136 halves/row
constexpr int A_STAGE = BM * ASTR;        // 5120 halves
constexpr int B_STAGE = BK * BSTR;        // 4352 halves
constexpr size_t SMEM_BYTES = (size_t)STAGES * (A_STAGE + B_STAGE) * sizeof(__half); // 75776

// Scratch (allocation-free: __device__ globals)
__device__ __align__(256) __half g_xh [(size_t)BD * DD];
__device__ __align__(256) __half g_w1h[(size_t)ED * DD * HD];
__device__ __align__(256) __half g_w2h[(size_t)ED * HD * DD];
__device__ __align__(256) __half g_h  [(size_t)ED * BD * HD];

// ---------------------------------------------------------------- converts
__global__ void cvt_f32_f16(const float* __restrict__ s, __half* __restrict__ d, int n4) {
    int i = blockIdx.x * blockDim.x + threadIdx.x;
    if (i < n4) {
        float4 v = reinterpret_cast<const float4*>(s)[i];
        reinterpret_cast<__half2*>(d)[2*i]   = __floats2half2_rn(v.x, v.y);
        reinterpret_cast<__half2*>(d)[2*i+1] = __floats2half2_rn(v.z, v.w);
    }
}

// ---------------------------------------------------------------- PTX utils
__device__ __forceinline__ void cp16(uint32_t saddr, const void* g) {
    asm volatile("cp.async.cg.shared.global [%0], [%1], 16;\n" :: "r"(saddr), "l"(g));
}
__device__ __forceinline__ void cp_commit() { asm volatile("cp.async.commit_group;\n"); }
template<int N> __device__ __forceinline__ void cp_wait() {
    asm volatile("cp.async.wait_group %0;\n" :: "n"(N));
}
__device__ __forceinline__ void ldsm4(uint32_t* r, uint32_t saddr) {
    asm volatile("ldmatrix.sync.aligned.m8n8.x4.shared.b16 {%0,%1,%2,%3}, [%4];\n"
        : "=r"(r[0]), "=r"(r[1]), "=r"(r[2]), "=r"(r[3]) : "r"(saddr));
}
__device__ __forceinline__ void ldsm4t(uint32_t* r, uint32_t saddr) {
    asm volatile("ldmatrix.sync.aligned.m8n8.x4.trans.shared.b16 {%0,%1,%2,%3}, [%4];\n"
        : "=r"(r[0]), "=r"(r[1]), "=r"(r[2]), "=r"(r[3]) : "r"(saddr));
}
__device__ __forceinline__ void mma16816(float* c, const uint32_t* a, uint32_t b0, uint32_t b1) {
    asm volatile("mma.sync.aligned.m16n8k16.row.col.f32.f16.f16.f32 "
        "{%0,%1,%2,%3}, {%4,%5,%6,%7}, {%8,%9}, {%0,%1,%2,%3};\n"
        : "+f"(c[0]), "+f"(c[1]), "+f"(c[2]), "+f"(c[3])
        : "r"(a[0]), "r"(a[1]), "r"(a[2]), "r"(a[3]), "r"(b0), "r"(b1));
}

// ---------------------------------------------------------------- GEMM
// C[M,N] = A[M,K] (row-major fp16) * B[K,N] (row-major fp16) per blockIdx.z expert.
// MODE 0: out = fp16, relu(C + bias)  (GEMM1 -> h scratch)
// MODE 1: out = fp32, C + bias        (GEMM2 -> final out, strided rows)
template<int MODE>
__global__ __launch_bounds__(256, 2)
void gemm_kernel(const __half* __restrict__ A, const __half* __restrict__ Bm,
                 const float* __restrict__ bias, void* __restrict__ outp,
                 int M, int N, int K,
                 size_t a_zstride, size_t out_zstride, size_t out_rstride)
{
    extern __shared__ __align__(16) __half smem[];
    const int z  = blockIdx.z;
    const int m0 = blockIdx.y * BM;
    const int n0 = blockIdx.x * BN;

    const __half* Az  = A + (size_t)z * a_zstride;
    const __half* Bz  = Bm + (size_t)z * (size_t)K * N;
    const float*  biz = bias + (size_t)z * N;

    const uint32_t sbase = (uint32_t)__cvta_generic_to_shared(smem);
    const uint32_t sA = sbase;
    const uint32_t sB = sbase + (uint32_t)(STAGES * A_STAGE * 2);

    const int tid = threadIdx.x;
    const int lane = tid & 31;
    const int warp = tid >> 5;
    const int wm = (warp >> 2) * 64;          // 2 warps along M
    const int wn = (warp & 3) * 32;           // 4 warps along N
    const int lr = (lane & 7) + ((lane >> 3) & 1) * 8;  // ldmatrix row-in-16
    const int lc = ((lane >> 4) & 1) * 8;               // ldmatrix col-half

    // Per-warp LDSM base addresses (stage 0); stage adds constant offsets.
    const uint32_t aBase = sA + (uint32_t)((wm + lr) * ASTR + lc) * 2;
    const uint32_t bBase = sB + (uint32_t)(lr * BSTR + wn + lc) * 2;

    auto load_stage = [&](int st, int kt) {
        const __half* Ag = Az + (size_t)m0 * K + (size_t)kt * BK;
        const __half* Bg = Bz + (size_t)kt * BK * N + n0;
        #pragma unroll
        for (int it = 0; it < 2; it++) {
            int c = tid + it * 256;
            int ar = c >> 2, ak = (c & 3) * 8;
            cp16(sA + (uint32_t)(st * A_STAGE + ar * ASTR + ak) * 2,
                 Ag + (size_t)ar * K + ak);
            int br = c >> 4, bn = (c & 15) * 8;
            cp16(sB + (uint32_t)(st * B_STAGE + br * BSTR + bn) * 2,
                 Bg + (size_t)br * N + bn);
        }
    };

    float acc[4][4][4] = {};

    // Software-pipelined stage: B fragments for the whole stage preloaded,
    // A fragments in a 2-deep ring across the 8 (ks, mt) steps.
    auto compute_stage = [&](int st) {
        uint32_t bf[2][2][4];   // [ks][nt][4]
        #pragma unroll
        for (int ks = 0; ks < 2; ks++)
            #pragma unroll
            for (int nt = 0; nt < 2; nt++)
                ldsm4t(bf[ks][nt],
                       bBase + (uint32_t)(st * B_STAGE + ks * 16 * BSTR + nt * 16) * 2);

        uint32_t af[2][4];
        ldsm4(af[0], aBase + (uint32_t)(st * A_STAGE) * 2);   // (ks=0, mt=0)
        #pragma unroll
        for (int i = 0; i < 8; i++) {                          // i = ks*4 + mt
            if (i + 1 < 8) {
                int ksn = (i + 1) >> 2, mtn = (i + 1) & 3;
                ldsm4(af[(i + 1) & 1],
                      aBase + (uint32_t)(st * A_STAGE + mtn * 16 * ASTR + ksn * 16) * 2);
            }
            int ks = i >> 2, mt = i & 3;
            #pragma unroll
            for (int n8 = 0; n8 < 4; n8++)
                mma16816(acc[mt][n8], af[i & 1],
                         bf[ks][n8 >> 1][(n8 & 1) * 2], bf[ks][n8 >> 1][(n8 & 1) * 2 + 1]);
        }
    };

    const int KT = K / BK;   // 32 (GEMM1) or 64 (GEMM2): divisible by 4
    load_stage(0, 0); cp_commit();
    load_stage(1, 1); cp_commit();
    load_stage(2, 2); cp_commit();
    cp_wait<2>();
    __syncthreads();

    // K loop unrolled by STAGES so stage indices are compile-time constants.
    #define PIPE_ITER(SC, SL)                                   \
        do {                                                    \
            if (kt + 3 < KT) load_stage(SL, kt + 3);            \
            cp_commit();                                        \
            compute_stage(SC);                                  \
            cp_wait<2>();                                       \
            __syncthreads();                                    \
            kt++;                                               \
        } while (0)

    int kt = 0;
    while (kt < KT) {
        PIPE_ITER(0, 3);
        PIPE_ITER(1, 0);
        PIPE_ITER(2, 1);
        PIPE_ITER(3, 2);
    }
    #undef PIPE_ITER

    // Epilogue
    const int g = lane >> 2, t4 = lane & 3;
    if (MODE == 0) {
        __half* O = (__half*)outp + (size_t)z * out_zstride;
        #pragma unroll
        for (int mt = 0; mt < 4; mt++) {
            int r0 = m0 + wm + mt * 16 + g;
            #pragma unroll
            for (int n8 = 0; n8 < 4; n8++) {
                int col = n0 + wn + n8 * 8 + 2 * t4;
                float bb0 = biz[col], bb1 = biz[col + 1];
                float v00 = fmaxf(acc[mt][n8][0] + bb0, 0.f);
                float v01 = fmaxf(acc[mt][n8][1] + bb1, 0.f);
                float v10 = fmaxf(acc[mt][n8][2] + bb0, 0.f);
                float v11 = fmaxf(acc[mt][n8][3] + bb1, 0.f);
                *(__half2*)&O[(size_t)r0 * out_rstride + col]       = __floats2half2_rn(v00, v01);
                *(__half2*)&O[(size_t)(r0 + 8) * out_rstride + col] = __floats2half2_rn(v10, v11);
            }
        }
    } else {
        float* O = (float*)outp + (size_t)z * out_zstride;
        #pragma unroll
        for (int mt = 0; mt < 4; mt++) {
            int r0 = m0 + wm + mt * 16 + g;
            #pragma unroll
            for (int n8 = 0; n8 < 4; n8++) {
                int col = n0 + wn + n8 * 8 + 2 * t4;
                float bb0 = biz[col], bb1 = biz[col + 1];
                float2 lo = make_float2(acc[mt][n8][0] + bb0, acc[mt][n8][1] + bb1);
                float2 hi = make_float2(acc[mt][n8][2] + bb0, acc[mt][n8][3] + bb1);
                *(float2*)&O[(size_t)r0 * out_rstride + col]       = lo;
                *(float2*)&O[(size_t)(r0 + 8) * out_rstride + col] = hi;
            }
        }
    }
}

// ---------------------------------------------------------------- launch
extern "C" void kernel_launch(void* const* d_in, const int* in_sizes, int n_in,
                              void* d_out, int out_size) {
    const float* x  = (const float*)d_in[0];   // [B, D]
    const float* W1 = (const float*)d_in[1];   // [E, D, H]
    const float* b1 = (const float*)d_in[2];   // [E, H]
    const float* W2 = (const float*)d_in[3];   // [E, H, D]
    const float* b2 = (const float*)d_in[4];   // [E, D]
    float* out = (float*)d_out;                // [B, E, D]

    __half *xh, *w1h, *w2h, *hbuf;
    cudaGetSymbolAddress((void**)&xh,  g_xh);
    cudaGetSymbolAddress((void**)&w1h, g_w1h);
    cudaGetSymbolAddress((void**)&w2h, g_w2h);
    cudaGetSymbolAddress((void**)&hbuf, g_h);

    cudaFuncSetAttribute(gemm_kernel<0>, cudaFuncAttributeMaxDynamicSharedMemorySize, (int)SMEM_BYTES);
    cudaFuncSetAttribute(gemm_kernel<1>, cudaFuncAttributeMaxDynamicSharedMemorySize, (int)SMEM_BYTES);

    int n4;
    n4 = (BD * DD) / 4;      cvt_f32_f16<<<(n4 + 255) / 256, 256>>>(x,  xh,  n4);
    n4 = (ED * DD * HD) / 4; cvt_f32_f16<<<(n4 + 255) / 256, 256>>>(W1, w1h, n4);
    n4 = (ED * HD * DD) / 4; cvt_f32_f16<<<(n4 + 255) / 256, 256>>>(W2, w2h, n4);

    // GEMM1: h[e,b,:] = relu(x @ W1_e + b1_e), fp16 out
    dim3 g1(HD / BN, BD / BM, ED);
    gemm_kernel<0><<<g1, 256, SMEM_BYTES>>>(xh, w1h, b1, hbuf,
        BD, HD, DD, /*a_zstride=*/0, /*out_zstride=*/(size_t)BD * HD, /*out_rstride=*/HD);

    // GEMM2: out[b,e,:] = h_e @ W2_e + b2_e, fp32 out with row stride E*D
    dim3 g2(DD / BN, BD / BM, ED);
    gemm_kernel<1><<<g2, 256, SMEM_BYTES>>>(hbuf, w2h, b2, out,
        BD, DD, HD, /*a_zstride=*/(size_t)BD * HD, /*out_zstride=*/(size_t)DD,
        /*out_rstride=*/(size_t)ED * DD);
}

// round 10
// speedup vs baseline: 1.1122x; 1.0387x over previous
#include <cuda_runtime.h>
#include <cuda_fp16.h>
#include <cstdint>

// Problem shape (fixed by the reference)
constexpr int BD = 4096;   // batch rows
constexpr int DD = 1024;   // model dim
constexpr int HD = 2048;   // hidden dim
constexpr int ED = 8;      // experts

// GEMM tiling: 128x128x32 CTA tile, 64x32 warp tile, 8 warps, 2 CTAs/SM.
// 5-stage cp.async ring, prefetch distance 4, wait_group<3>.
constexpr int BM = 128, BN = 128, BK = 32;
constexpr int STAGES = 5;
constexpr int ASTR = BK + 8;              // 40 halves/row
constexpr int BSTR = BN + 8;              // 136 halves/row
constexpr int A_STAGE = BM * ASTR;        // 5120 halves
constexpr int B_STAGE = BK * BSTR;        // 4352 halves
constexpr size_t SMEM_BYTES = (size_t)STAGES * (A_STAGE + B_STAGE) * sizeof(__half); // 94720

// Scratch (allocation-free: __device__ globals)
__device__ __align__(256) __half g_xh [(size_t)BD * DD];
__device__ __align__(256) __half g_w1h[(size_t)ED * DD * HD];
__device__ __align__(256) __half g_w2h[(size_t)ED * HD * DD];
__device__ __align__(256) __half g_h  [(size_t)ED * BD * HD];

// Convert ranges (in float4 units)
constexpr int N4_X  = (BD * DD) / 4;           // 1048576
constexpr int N4_W1 = (ED * DD * HD) / 4;      // 4194304
constexpr int N4_W2 = (ED * HD * DD) / 4;      // 4194304
constexpr int N4_TOTAL = N4_X + N4_W1 + N4_W2;

// ---------------------------------------------------------------- fused convert
__global__ void cvt_all(const float* __restrict__ x, const float* __restrict__ W1,
                        const float* __restrict__ W2,
                        __half* __restrict__ xh, __half* __restrict__ w1h,
                        __half* __restrict__ w2h) {
    int i = blockIdx.x * blockDim.x + threadIdx.x;
    if (i >= N4_TOTAL) return;
    const float* s;
    __half* d;
    int j;
    if (i < N4_X)            { s = x;  d = xh;  j = i; }
    else if (i < N4_X + N4_W1) { s = W1; d = w1h; j = i - N4_X; }
    else                     { s = W2; d = w2h; j = i - N4_X - N4_W1; }
    float4 v = reinterpret_cast<const float4*>(s)[j];
    reinterpret_cast<__half2*>(d)[2*j]   = __floats2half2_rn(v.x, v.y);
    reinterpret_cast<__half2*>(d)[2*j+1] = __floats2half2_rn(v.z, v.w);
}

// ---------------------------------------------------------------- PTX utils
__device__ __forceinline__ void cp16(uint32_t saddr, const void* g) {
    asm volatile("cp.async.cg.shared.global [%0], [%1], 16;\n" :: "r"(saddr), "l"(g));
}
__device__ __forceinline__ void cp_commit() { asm volatile("cp.async.commit_group;\n"); }
template<int N> __device__ __forceinline__ void cp_wait() {
    asm volatile("cp.async.wait_group %0;\n" :: "n"(N));
}
__device__ __forceinline__ void ldsm4(uint32_t* r, uint32_t saddr) {
    asm volatile("ldmatrix.sync.aligned.m8n8.x4.shared.b16 {%0,%1,%2,%3}, [%4];\n"
        : "=r"(r[0]), "=r"(r[1]), "=r"(r[2]), "=r"(r[3]) : "r"(saddr));
}
__device__ __forceinline__ void ldsm4t(uint32_t* r, uint32_t saddr) {
    asm volatile("ldmatrix.sync.aligned.m8n8.x4.trans.shared.b16 {%0,%1,%2,%3}, [%4];\n"
        : "=r"(r[0]), "=r"(r[1]), "=r"(r[2]), "=r"(r[3]) : "r"(saddr));
}
__device__ __forceinline__ void mma16816(float* c, const uint32_t* a, uint32_t b0, uint32_t b1) {
    asm volatile("mma.sync.aligned.m16n8k16.row.col.f32.f16.f16.f32 "
        "{%0,%1,%2,%3}, {%4,%5,%6,%7}, {%8,%9}, {%0,%1,%2,%3};\n"
        : "+f"(c[0]), "+f"(c[1]), "+f"(c[2]), "+f"(c[3])
        : "r"(a[0]), "r"(a[1]), "r"(a[2]), "r"(a[3]), "r"(b0), "r"(b1));
}

// ---------------------------------------------------------------- GEMM
// C[M,N] = A[M,K] (row-major fp16) * B[K,N] (row-major fp16) per blockIdx.z expert.
// MODE 0: out = fp16, relu(C + bias)  (GEMM1 -> h scratch)
// MODE 1: out = fp32, C + bias        (GEMM2 -> final out, strided rows)
template<int MODE>
__global__ __launch_bounds__(256, 2)
void gemm_kernel(const __half* __restrict__ A, const __half* __restrict__ Bm,
                 const float* __restrict__ bias, void* __restrict__ outp,
                 int M, int N, int K,
                 size_t a_zstride, size_t out_zstride, size_t out_rstride)
{
    extern __shared__ __align__(16) __half smem[];
    const int z  = blockIdx.z;
    const int m0 = blockIdx.y * BM;
    const int n0 = blockIdx.x * BN;

    const __half* Az  = A + (size_t)z * a_zstride;
    const __half* Bz  = Bm + (size_t)z * (size_t)K * N;
    const float*  biz = bias + (size_t)z * N;

    const uint32_t sbase = (uint32_t)__cvta_generic_to_shared(smem);
    const uint32_t sA = sbase;
    const uint32_t sB = sbase + (uint32_t)(STAGES * A_STAGE * 2);

    const int tid = threadIdx.x;
    const int lane = tid & 31;
    const int warp = tid >> 5;
    const int wm = (warp >> 2) * 64;          // 2 warps along M
    const int wn = (warp & 3) * 32;           // 4 warps along N
    const int lr = (lane & 7) + ((lane >> 3) & 1) * 8;  // ldmatrix row-in-16
    const int lc = ((lane >> 4) & 1) * 8;               // ldmatrix col-half

    auto load_stage = [&](int st, int kt) {
        const __half* Ag = Az + (size_t)m0 * K + (size_t)kt * BK;
        const __half* Bg = Bz + (size_t)kt * BK * N + n0;
        #pragma unroll
        for (int it = 0; it < 2; it++) {
            int c = tid + it * 256;
            int ar = c >> 2, ak = (c & 3) * 8;
            cp16(sA + (uint32_t)(st * A_STAGE + ar * ASTR + ak) * 2,
                 Ag + (size_t)ar * K + ak);
            int br = c >> 4, bn = (c & 15) * 8;
            cp16(sB + (uint32_t)(st * B_STAGE + br * BSTR + bn) * 2,
                 Bg + (size_t)br * N + bn);
        }
    };

    float acc[4][4][4] = {};

    auto compute_stage = [&](int st) {
        #pragma unroll
        for (int ks = 0; ks < BK / 16; ks++) {
            uint32_t af[4][4];
            #pragma unroll
            for (int mt = 0; mt < 4; mt++)
                ldsm4(af[mt], sA + (uint32_t)(st * A_STAGE + (wm + mt*16 + lr) * ASTR + ks*16 + lc) * 2);
            uint32_t bf[2][4];
            #pragma unroll
            for (int nt = 0; nt < 2; nt++)
                ldsm4t(bf[nt], sB + (uint32_t)(st * B_STAGE + (ks*16 + lr) * BSTR + wn + nt*16 + lc) * 2);
            #pragma unroll
            for (int mt = 0; mt < 4; mt++)
                #pragma unroll
                for (int n8 = 0; n8 < 4; n8++)
                    mma16816(acc[mt][n8], af[mt],
                             bf[n8 >> 1][(n8 & 1) * 2], bf[n8 >> 1][(n8 & 1) * 2 + 1]);
        }
    };

    const int KT = K / BK;
    // Prologue: fill 4 stages (prefetch distance 4)
    load_stage(0, 0); cp_commit();
    load_stage(1, 1); cp_commit();
    load_stage(2, 2); cp_commit();
    load_stage(3, 3); cp_commit();
    cp_wait<3>();                 // chunk 0 resident
    __syncthreads();

    int buf = 0;        // stage being computed (ring of 5)
    int ldb = 4;        // stage being loaded next
    for (int kt = 0; kt < KT; kt++) {
        if (kt + 4 < KT) load_stage(ldb, kt + 4);
        cp_commit();
        compute_stage(buf);
        cp_wait<3>();   // chunk kt+1 resident; up to 3 younger groups in flight
        __syncthreads();
        buf = (buf + 1 == STAGES) ? 0 : buf + 1;
        ldb = (ldb + 1 == STAGES) ? 0 : ldb + 1;
    }

    // Epilogue
    const int g = lane >> 2, t4 = lane & 3;
    if (MODE == 0) {
        __half* O = (__half*)outp + (size_t)z * out_zstride;
        #pragma unroll
        for (int mt = 0; mt < 4; mt++) {
            int r0 = m0 + wm + mt * 16 + g;
            #pragma unroll
            for (int n8 = 0; n8 < 4; n8++) {
                int col = n0 + wn + n8 * 8 + 2 * t4;
                float bb0 = biz[col], bb1 = biz[col + 1];
                float v00 = fmaxf(acc[mt][n8][0] + bb0, 0.f);
                float v01 = fmaxf(acc[mt][n8][1] + bb1, 0.f);
                float v10 = fmaxf(acc[mt][n8][2] + bb0, 0.f);
                float v11 = fmaxf(acc[mt][n8][3] + bb1, 0.f);
                *(__half2*)&O[(size_t)r0 * out_rstride + col]       = __floats2half2_rn(v00, v01);
                *(__half2*)&O[(size_t)(r0 + 8) * out_rstride + col] = __floats2half2_rn(v10, v11);
            }
        }
    } else {
        float* O = (float*)outp + (size_t)z * out_zstride;
        #pragma unroll
        for (int mt = 0; mt < 4; mt++) {
            int r0 = m0 + wm + mt * 16 + g;
            #pragma unroll
            for (int n8 = 0; n8 < 4; n8++) {
                int col = n0 + wn + n8 * 8 + 2 * t4;
                float bb0 = biz[col], bb1 = biz[col + 1];
                float2 lo = make_float2(acc[mt][n8][0] + bb0, acc[mt][n8][1] + bb1);
                float2 hi = make_float2(acc[mt][n8][2] + bb0, acc[mt][n8][3] + bb1);
                *(float2*)&O[(size_t)r0 * out_rstride + col]       = lo;
                *(float2*)&O[(size_t)(r0 + 8) * out_rstride + col] = hi;
            }
        }
    }
}

// ---------------------------------------------------------------- launch
extern "C" void kernel_launch(void* const* d_in, const int* in_sizes, int n_in,
                              void* d_out, int out_size) {
    const float* x  = (const float*)d_in[0];   // [B, D]
    const float* W1 = (const float*)d_in[1];   // [E, D, H]
    const float* b1 = (const float*)d_in[2];   // [E, H]
    const float* W2 = (const float*)d_in[3];   // [E, H, D]
    const float* b2 = (const float*)d_in[4];   // [E, D]
    float* out = (float*)d_out;                // [B, E, D]

    __half *xh, *w1h, *w2h, *hbuf;
    cudaGetSymbolAddress((void**)&xh,  g_xh);
    cudaGetSymbolAddress((void**)&w1h, g_w1h);
    cudaGetSymbolAddress((void**)&w2h, g_w2h);
    cudaGetSymbolAddress((void**)&hbuf, g_h);

    cudaFuncSetAttribute(gemm_kernel<0>, cudaFuncAttributeMaxDynamicSharedMemorySize, (int)SMEM_BYTES);
    cudaFuncSetAttribute(gemm_kernel<1>, cudaFuncAttributeMaxDynamicSharedMemorySize, (int)SMEM_BYTES);

    // One fused convert launch (x, W1, W2 -> fp16)
    cvt_all<<<(N4_TOTAL + 255) / 256, 256>>>(x, W1, W2, xh, w1h, w2h);

    // GEMM1: h[e,b,:] = relu(x @ W1_e + b1_e), fp16 out
    dim3 g1(HD / BN, BD / BM, ED);
    gemm_kernel<0><<<g1, 256, SMEM_BYTES>>>(xh, w1h, b1, hbuf,
        BD, HD, DD, /*a_zstride=*/0, /*out_zstride=*/(size_t)BD * HD, /*out_rstride=*/HD);

    // GEMM2: out[b,e,:] = h_e @ W2_e + b2_e, fp32 out with row stride E*D
    dim3 g2(DD / BN, BD / BM, ED);
    gemm_kernel<1><<<g2, 256, SMEM_BYTES>>>(hbuf, w2h, b2, out,
        BD, DD, HD, /*a_zstride=*/(size_t)BD * HD, /*out_zstride=*/(size_t)DD,
        /*out_rstride=*/(size_t)ED * DD);
}

// round 11
// speedup vs baseline: 1.1177x; 1.0050x over previous
#include <cuda_runtime.h>
#include <cuda_fp16.h>
#include <cstdint>

// Problem shape (fixed by the reference)
constexpr int BD = 4096;   // batch rows
constexpr int DD = 1024;   // model dim
constexpr int HD = 2048;   // hidden dim
constexpr int ED = 8;      // experts

// GEMM tiling: 128x128x32 CTA tile, 64x32 warp tile, 8 warps, 2 CTAs/SM.
// 5-stage cp.async ring, prefetch distance 4, wait_group<3>.  (R10 best config)
constexpr int BM = 128, BN = 128, BK = 32;
constexpr int STAGES = 5;
constexpr int ASTR = BK + 8;              // 40 halves/row
constexpr int BSTR = BN + 8;              // 136 halves/row
constexpr int A_STAGE = BM * ASTR;        // 5120 halves
constexpr int B_STAGE = BK * BSTR;        // 4352 halves
constexpr size_t SMEM_BYTES = (size_t)STAGES * (A_STAGE + B_STAGE) * sizeof(__half); // 94720

// Scratch (allocation-free: __device__ globals)
__device__ __align__(256) __half g_xh [(size_t)BD * DD];
__device__ __align__(256) __half g_w1h[(size_t)ED * DD * HD];
__device__ __align__(256) __half g_w2h[(size_t)ED * HD * DD];
__device__ __align__(256) __half g_h  [(size_t)ED * BD * HD];

// Convert ranges in float8 (32B) units
constexpr int N8_X  = (BD * DD) / 8;           // 524288
constexpr int N8_W1 = (ED * DD * HD) / 8;      // 2097152
constexpr int N8_W2 = (ED * HD * DD) / 8;      // 2097152
constexpr int N8_TOTAL = N8_X + N8_W1 + N8_W2; // 4718592

// ---------------------------------------------------------------- fused convert
// Each thread: 2x float4 load (32B) -> 1x uint4 store (16B of 8 halves).
// Grid-stride over a wave-aligned grid.
__global__ void cvt_all(const float* __restrict__ x, const float* __restrict__ W1,
                        const float* __restrict__ W2,
                        __half* __restrict__ xh, __half* __restrict__ w1h,
                        __half* __restrict__ w2h) {
    for (int i = blockIdx.x * blockDim.x + threadIdx.x; i < N8_TOTAL;
         i += gridDim.x * blockDim.x) {
        const float4* s;
        uint4* d;
        int j;
        if (i < N8_X)              { s = (const float4*)x;  d = (uint4*)xh;  j = i; }
        else if (i < N8_X + N8_W1) { s = (const float4*)W1; d = (uint4*)w1h; j = i - N8_X; }
        else                       { s = (const float4*)W2; d = (uint4*)w2h; j = i - N8_X - N8_W1; }
        float4 v0 = s[2 * j];
        float4 v1 = s[2 * j + 1];
        __half2 h0 = __floats2half2_rn(v0.x, v0.y);
        __half2 h1 = __floats2half2_rn(v0.z, v0.w);
        __half2 h2 = __floats2half2_rn(v1.x, v1.y);
        __half2 h3 = __floats2half2_rn(v1.z, v1.w);
        uint4 o;
        o.x = *reinterpret_cast<uint32_t*>(&h0);
        o.y = *reinterpret_cast<uint32_t*>(&h1);
        o.z = *reinterpret_cast<uint32_t*>(&h2);
        o.w = *reinterpret_cast<uint32_t*>(&h3);
        d[j] = o;
    }
}

// ---------------------------------------------------------------- PTX utils
__device__ __forceinline__ void cp16(uint32_t saddr, const void* g) {
    asm volatile("cp.async.cg.shared.global [%0], [%1], 16;\n" :: "r"(saddr), "l"(g));
}
__device__ __forceinline__ void cp_commit() { asm volatile("cp.async.commit_group;\n"); }
template<int N> __device__ __forceinline__ void cp_wait() {
    asm volatile("cp.async.wait_group %0;\n" :: "n"(N));
}
__device__ __forceinline__ void ldsm4(uint32_t* r, uint32_t saddr) {
    asm volatile("ldmatrix.sync.aligned.m8n8.x4.shared.b16 {%0,%1,%2,%3}, [%4];\n"
        : "=r"(r[0]), "=r"(r[1]), "=r"(r[2]), "=r"(r[3]) : "r"(saddr));
}
__device__ __forceinline__ void ldsm4t(uint32_t* r, uint32_t saddr) {
    asm volatile("ldmatrix.sync.aligned.m8n8.x4.trans.shared.b16 {%0,%1,%2,%3}, [%4];\n"
        : "=r"(r[0]), "=r"(r[1]), "=r"(r[2]), "=r"(r[3]) : "r"(saddr));
}
__device__ __forceinline__ void mma16816(float* c, const uint32_t* a, uint32_t b0, uint32_t b1) {
    asm volatile("mma.sync.aligned.m16n8k16.row.col.f32.f16.f16.f32 "
        "{%0,%1,%2,%3}, {%4,%5,%6,%7}, {%8,%9}, {%0,%1,%2,%3};\n"
        : "+f"(c[0]), "+f"(c[1]), "+f"(c[2]), "+f"(c[3])
        : "r"(a[0]), "r"(a[1]), "r"(a[2]), "r"(a[3]), "r"(b0), "r"(b1));
}

// ---------------------------------------------------------------- GEMM (R10 best)
// C[M,N] = A[M,K] (row-major fp16) * B[K,N] (row-major fp16) per blockIdx.z expert.
// MODE 0: out = fp16, relu(C + bias)  (GEMM1 -> h scratch)
// MODE 1: out = fp32, C + bias        (GEMM2 -> final out, strided rows)
template<int MODE>
__global__ __launch_bounds__(256, 2)
void gemm_kernel(const __half* __restrict__ A, const __half* __restrict__ Bm,
                 const float* __restrict__ bias, void* __restrict__ outp,
                 int M, int N, int K,
                 size_t a_zstride, size_t out_zstride, size_t out_rstride)
{
    extern __shared__ __align__(16) __half smem[];
    const int z  = blockIdx.z;
    const int m0 = blockIdx.y * BM;
    const int n0 = blockIdx.x * BN;

    const __half* Az  = A + (size_t)z * a_zstride;
    const __half* Bz  = Bm + (size_t)z * (size_t)K * N;
    const float*  biz = bias + (size_t)z * N;

    const uint32_t sbase = (uint32_t)__cvta_generic_to_shared(smem);
    const uint32_t sA = sbase;
    const uint32_t sB = sbase + (uint32_t)(STAGES * A_STAGE * 2);

    const int tid = threadIdx.x;
    const int lane = tid & 31;
    const int warp = tid >> 5;
    const int wm = (warp >> 2) * 64;          // 2 warps along M
    const int wn = (warp & 3) * 32;           // 4 warps along N
    const int lr = (lane & 7) + ((lane >> 3) & 1) * 8;  // ldmatrix row-in-16
    const int lc = ((lane >> 4) & 1) * 8;               // ldmatrix col-half

    auto load_stage = [&](int st, int kt) {
        const __half* Ag = Az + (size_t)m0 * K + (size_t)kt * BK;
        const __half* Bg = Bz + (size_t)kt * BK * N + n0;
        #pragma unroll
        for (int it = 0; it < 2; it++) {
            int c = tid + it * 256;
            int ar = c >> 2, ak = (c & 3) * 8;
            cp16(sA + (uint32_t)(st * A_STAGE + ar * ASTR + ak) * 2,
                 Ag + (size_t)ar * K + ak);
            int br = c >> 4, bn = (c & 15) * 8;
            cp16(sB + (uint32_t)(st * B_STAGE + br * BSTR + bn) * 2,
                 Bg + (size_t)br * N + bn);
        }
    };

    float acc[4][4][4] = {};

    auto compute_stage = [&](int st) {
        #pragma unroll
        for (int ks = 0; ks < BK / 16; ks++) {
            uint32_t af[4][4];
            #pragma unroll
            for (int mt = 0; mt < 4; mt++)
                ldsm4(af[mt], sA + (uint32_t)(st * A_STAGE + (wm + mt*16 + lr) * ASTR + ks*16 + lc) * 2);
            uint32_t bf[2][4];
            #pragma unroll
            for (int nt = 0; nt < 2; nt++)
                ldsm4t(bf[nt], sB + (uint32_t)(st * B_STAGE + (ks*16 + lr) * BSTR + wn + nt*16 + lc) * 2);
            #pragma unroll
            for (int mt = 0; mt < 4; mt++)
                #pragma unroll
                for (int n8 = 0; n8 < 4; n8++)
                    mma16816(acc[mt][n8], af[mt],
                             bf[n8 >> 1][(n8 & 1) * 2], bf[n8 >> 1][(n8 & 1) * 2 + 1]);
        }
    };

    const int KT = K / BK;
    load_stage(0, 0); cp_commit();
    load_stage(1, 1); cp_commit();
    load_stage(2, 2); cp_commit();
    load_stage(3, 3); cp_commit();
    cp_wait<3>();                 // chunk 0 resident
    __syncthreads();

    int buf = 0;        // stage being computed (ring of 5)
    int ldb = 4;        // stage being loaded next
    for (int kt = 0; kt < KT; kt++) {
        if (kt + 4 < KT) load_stage(ldb, kt + 4);
        cp_commit();
        compute_stage(buf);
        cp_wait<3>();
        __syncthreads();
        buf = (buf + 1 == STAGES) ? 0 : buf + 1;
        ldb = (ldb + 1 == STAGES) ? 0 : ldb + 1;
    }

    // Epilogue
    const int g = lane >> 2, t4 = lane & 3;
    if (MODE == 0) {
        __half* O = (__half*)outp + (size_t)z * out_zstride;
        #pragma unroll
        for (int mt = 0; mt < 4; mt++) {
            int r0 = m0 + wm + mt * 16 + g;
            #pragma unroll
            for (int n8 = 0; n8 < 4; n8++) {
                int col = n0 + wn + n8 * 8 + 2 * t4;
                float bb0 = biz[col], bb1 = biz[col + 1];
                float v00 = fmaxf(acc[mt][n8][0] + bb0, 0.f);
                float v01 = fmaxf(acc[mt][n8][1] + bb1, 0.f);
                float v10 = fmaxf(acc[mt][n8][2] + bb0, 0.f);
                float v11 = fmaxf(acc[mt][n8][3] + bb1, 0.f);
                *(__half2*)&O[(size_t)r0 * out_rstride + col]       = __floats2half2_rn(v00, v01);
                *(__half2*)&O[(size_t)(r0 + 8) * out_rstride + col] = __floats2half2_rn(v10, v11);
            }
        }
    } else {
        float* O = (float*)outp + (size_t)z * out_zstride;
        #pragma unroll
        for (int mt = 0; mt < 4; mt++) {
            int r0 = m0 + wm + mt * 16 + g;
            #pragma unroll
            for (int n8 = 0; n8 < 4; n8++) {
                int col = n0 + wn + n8 * 8 + 2 * t4;
                float bb0 = biz[col], bb1 = biz[col + 1];
                float2 lo = make_float2(acc[mt][n8][0] + bb0, acc[mt][n8][1] + bb1);
                float2 hi = make_float2(acc[mt][n8][2] + bb0, acc[mt][n8][3] + bb1);
                *(float2*)&O[(size_t)r0 * out_rstride + col]       = lo;
                *(float2*)&O[(size_t)(r0 + 8) * out_rstride + col] = hi;
            }
        }
    }
}

// ---------------------------------------------------------------- launch
extern "C" void kernel_launch(void* const* d_in, const int* in_sizes, int n_in,
                              void* d_out, int out_size) {
    const float* x  = (const float*)d_in[0];   // [B, D]
    const float* W1 = (const float*)d_in[1];   // [E, D, H]
    const float* b1 = (const float*)d_in[2];   // [E, H]
    const float* W2 = (const float*)d_in[3];   // [E, H, D]
    const float* b2 = (const float*)d_in[4];   // [E, D]
    float* out = (float*)d_out;                // [B, E, D]

    __half *xh, *w1h, *w2h, *hbuf;
    cudaGetSymbolAddress((void**)&xh,  g_xh);
    cudaGetSymbolAddress((void**)&w1h, g_w1h);
    cudaGetSymbolAddress((void**)&w2h, g_w2h);
    cudaGetSymbolAddress((void**)&hbuf, g_h);

    cudaFuncSetAttribute(gemm_kernel<0>, cudaFuncAttributeMaxDynamicSharedMemorySize, (int)SMEM_BYTES);
    cudaFuncSetAttribute(gemm_kernel<1>, cudaFuncAttributeMaxDynamicSharedMemorySize, (int)SMEM_BYTES);

    int sm = 148;
    cudaDeviceGetAttribute(&sm, cudaDevAttrMultiProcessorCount, 0);

    // One fused convert launch, wave-aligned grid-stride (8 waves of 256-thr CTAs)
    cvt_all<<<sm * 8, 256>>>(x, W1, W2, xh, w1h, w2h);

    // GEMM1: h[e,b,:] = relu(x @ W1_e + b1_e), fp16 out
    dim3 g1(HD / BN, BD / BM, ED);
    gemm_kernel<0><<<g1, 256, SMEM_BYTES>>>(xh, w1h, b1, hbuf,
        BD, HD, DD, /*a_zstride=*/0, /*out_zstride=*/(size_t)BD * HD, /*out_rstride=*/HD);

    // GEMM2: out[b,e,:] = h_e @ W2_e + b2_e, fp32 out with row stride E*D
    dim3 g2(DD / BN, BD / BM, ED);
    gemm_kernel<1><<<g2, 256, SMEM_BYTES>>>(hbuf, w2h, b2, out,
        BD, DD, HD, /*a_zstride=*/(size_t)BD * HD, /*out_zstride=*/(size_t)DD,
        /*out_rstride=*/(size_t)ED * DD);
}